// round 14
// baseline (speedup 1.0000x reference)
#include <cuda_runtime.h>
#include <cuda_fp16.h>
#include <math.h>

#define NN      50000   // nodes
#define FF      128     // features
#define EE      600000  // edges (before self loops)
#define EP      (EE + NN)
#define NID     5000
#define SB      256
#define NSB     ((NN + SB - 1) / SB)   // 196
// dh = 16, scale = 0.25

// ---------------- device scratch (static; no allocations) ----------------
__device__ __half g_Qh[NN * FF];
__device__ __half g_Kh[NN * FF];
__device__ __half g_Vh[NN * FF];
__device__ __half g_Xh[NN * FF];          // x pre-converted to fp16
__device__ __half g_Wh[3 * FF * FF];      // Wq/Wk/Wv transposed to [n][k] fp16
__device__ int    g_deg[NN];      // zero-initialized at load; scan23 re-zeros it
__device__ int    g_offs[NN + 1];
__device__ int    g_cursor[NN];
__device__ int    g_scol[EP];
__device__ int    g_bsum[NSB];

// ---------------- helpers ----------------
__device__ __forceinline__ void mma_f16(float* c, const unsigned* a, const unsigned* b) {
    asm volatile(
        "mma.sync.aligned.m16n8k16.row.col.f32.f16.f16.f32 "
        "{%0,%1,%2,%3},{%4,%5,%6,%7},{%8,%9},{%0,%1,%2,%3};"
        : "+f"(c[0]), "+f"(c[1]), "+f"(c[2]), "+f"(c[3])
        : "r"(a[0]), "r"(a[1]), "r"(a[2]), "r"(a[3]), "r"(b[0]), "r"(b[1]));
}

__device__ __forceinline__ void cp_async16(void* dst_smem, const void* src) {
    unsigned d = (unsigned)__cvta_generic_to_shared(dst_smem);
    asm volatile("cp.async.cg.shared.global [%0], [%1], 16;" :: "r"(d), "l"(src));
}
__device__ __forceinline__ void cp_commit() {
    asm volatile("cp.async.commit_group;");
}
template <int N>
__device__ __forceinline__ void cp_wait() {
    asm volatile("cp.async.wait_group %0;" :: "n"(N));
}

// ---------------- prep: x -> fp16, W -> fp16 transposed [n][k] -------------
#define XB 6250                            // blocks for x (6.4M/4/256)
__global__ void prep_kernel(const float* __restrict__ x,
                            const float* __restrict__ Wq,
                            const float* __restrict__ Wk,
                            const float* __restrict__ Wv)
{
    const int b = blockIdx.x;
    if (b < XB) {
        const int i4 = (b * 256 + threadIdx.x) * 4;
        float4 v = *reinterpret_cast<const float4*>(&x[i4]);
        *reinterpret_cast<__half2*>(&g_Xh[i4])     = __floats2half2_rn(v.x, v.y);
        *reinterpret_cast<__half2*>(&g_Xh[i4 + 2]) = __floats2half2_rn(v.z, v.w);
    } else {
        const int idx = (b - XB) * 256 + threadIdx.x;   // 0..49151
        const int m = idx >> 14;
        const int rem = idx & 16383;
        const int k = rem >> 7, n = rem & 127;
        const float* W = (m == 0) ? Wq : (m == 1) ? Wk : Wv;
        g_Wh[m * 16384 + n * 128 + k] = __float2half(W[k * 128 + n]);
    }
}

// ---------------- fp16 QKV GEMM, 3-stage cp.async pipeline -----------------
// blockIdx.y: 0->Q(relu+bias), 1->K(relu+bias), 2->V(plain)
#define KC 32
#define HS 40                              // halves per smem row (32 + 8 pad)
#define CHUNK_H (128 * HS)                 // halves per A or B chunk
#define GEMM_SMEM (3 * 2 * CHUNK_H * 2)    // 3 stages x (A+B) x 2B = 61440

__global__ __launch_bounds__(256, 2) void gemm3_kernel(
    const float* __restrict__ bq, const float* __restrict__ bk)
{
    const int which = blockIdx.y;
    const float* bias = (which == 0) ? bq : (which == 1) ? bk : nullptr;
    __half* out = (which == 0) ? g_Qh : (which == 1) ? g_Kh : g_Vh;
    const __half* Wh = g_Wh + which * 16384;

    extern __shared__ __half hsmem[];

    const int tid  = threadIdx.x;
    const int lane = tid & 31;
    const int warp = tid >> 5;
    const int wm   = warp >> 1;
    const int wn   = warp & 1;
    const int rowBase = blockIdx.x * 128;

    const int g0   = tid * 2;                  // even
    const int row  = g0 >> 2;                  // same row for both granules
    const int c8a  = (g0 & 3) * 8;             // halves offset of granule 0
    const int c8b  = ((g0 + 1) & 3) * 8;       // granule 1
    const int gRow = min(rowBase + row, NN - 1);

    auto prefetch = [&](int c) {
        const int kc = c * KC;
        __half* As = hsmem + (c % 3) * 2 * CHUNK_H;
        __half* Bs = As + CHUNK_H;
        cp_async16(&As[row * HS + c8a], &g_Xh[(size_t)gRow * FF + kc + c8a]);
        cp_async16(&As[row * HS + c8b], &g_Xh[(size_t)gRow * FF + kc + c8b]);
        cp_async16(&Bs[row * HS + c8a], &Wh[(size_t)row * FF + kc + c8a]);
        cp_async16(&Bs[row * HS + c8b], &Wh[(size_t)row * FF + kc + c8b]);
        cp_commit();
    };

    float acc[2][8][4];
#pragma unroll
    for (int i = 0; i < 2; i++)
#pragma unroll
        for (int j = 0; j < 8; j++)
#pragma unroll
            for (int t = 0; t < 4; t++) acc[i][j][t] = 0.f;

    const int lq = lane >> 2;
    const int lr = lane & 3;

    prefetch(0);
    prefetch(1);

    for (int c = 0; c < 4; c++) {
        if (c + 2 < 4) { prefetch(c + 2); cp_wait<2>(); }
        else if (c + 1 < 4) cp_wait<1>();
        else cp_wait<0>();
        __syncthreads();

        const __half* Ab = hsmem + (c % 3) * 2 * CHUNK_H;
        const __half* Bb = Ab + CHUNK_H;
#pragma unroll
        for (int kk = 0; kk < 2; kk++) {
            const int bk16 = kk * 16 + 2 * lr;
            unsigned bf[8][2];
#pragma unroll
            for (int j = 0; j < 8; j++) {
                int n = wn * 64 + j * 8 + lq;
                bf[j][0] = *reinterpret_cast<const unsigned*>(&Bb[n * HS + bk16]);
                bf[j][1] = *reinterpret_cast<const unsigned*>(&Bb[n * HS + bk16 + 8]);
            }
            unsigned af[2][4];
#pragma unroll
            for (int i = 0; i < 2; i++) {
                int r0 = wm * 32 + i * 16 + lq;
                af[i][0] = *reinterpret_cast<const unsigned*>(&Ab[r0 * HS + bk16]);
                af[i][1] = *reinterpret_cast<const unsigned*>(&Ab[(r0 + 8) * HS + bk16]);
                af[i][2] = *reinterpret_cast<const unsigned*>(&Ab[r0 * HS + bk16 + 8]);
                af[i][3] = *reinterpret_cast<const unsigned*>(&Ab[(r0 + 8) * HS + bk16 + 8]);
            }
#pragma unroll
            for (int i = 0; i < 2; i++)
#pragma unroll
                for (int j = 0; j < 8; j++)
                    mma_f16(acc[i][j], af[i], bf[j]);
        }
        __syncthreads();
    }

    // ---- epilogue: bias (+relu) -> half2 store ----
#pragma unroll
    for (int i = 0; i < 2; i++) {
#pragma unroll
        for (int j = 0; j < 8; j++) {
            int col = wn * 64 + j * 8 + lr * 2;
            float b0 = 0.f, b1 = 0.f;
            if (which < 2) { b0 = bias[col]; b1 = bias[col + 1]; }
            int r0 = rowBase + wm * 32 + i * 16 + lq;
            int r1 = r0 + 8;
            float v00 = acc[i][j][0] + b0, v01 = acc[i][j][1] + b1;
            float v10 = acc[i][j][2] + b0, v11 = acc[i][j][3] + b1;
            if (which < 2) {
                v00 = fmaxf(v00, 0.f); v01 = fmaxf(v01, 0.f);
                v10 = fmaxf(v10, 0.f); v11 = fmaxf(v11, 0.f);
            }
            if (r0 < NN)
                *reinterpret_cast<__half2*>(&out[(size_t)r0 * FF + col]) =
                    __floats2half2_rn(v00, v01);
            if (r1 < NN)
                *reinterpret_cast<__half2*>(&out[(size_t)r1 * FF + col]) =
                    __floats2half2_rn(v10, v11);
        }
    }
}

// -------- id scatter GEMM: V[id] += x[id] @ kernel_id --------
#define IDB 16
__global__ __launch_bounds__(256) void idgemm_kernel(
    const float* __restrict__ x,
    const int* __restrict__ id_index,
    const float* __restrict__ Wid)
{
    __shared__ float xs[IDB][FF];
    __shared__ float red[IDB][FF];
    __shared__ int ids[IDB];

    const int tid = threadIdx.x;
    const int base = blockIdx.x * IDB;
    const int nid = min(IDB, NID - base);

    if (tid < nid) ids[tid] = id_index[base + tid];
    __syncthreads();

    for (int i = tid; i < IDB * FF; i += 256) {
        int r = i >> 7;
        if (r < nid) xs[r][i & 127] = x[(size_t)ids[r] * FF + (i & 127)];
    }
    __syncthreads();

    const int col = tid & 127;
    const int half = tid >> 7;
    float acc[IDB];
#pragma unroll
    for (int i = 0; i < IDB; i++) acc[i] = 0.f;

    const int k0 = half * 64;
#pragma unroll 4
    for (int k = k0; k < k0 + 64; k++) {
        const float w = Wid[k * FF + col];
#pragma unroll
        for (int i = 0; i < IDB; i++)
            acc[i] = fmaf(xs[i][k], w, acc[i]);
    }

    if (half == 1) {
#pragma unroll
        for (int i = 0; i < IDB; i++) red[i][col] = acc[i];
    }
    __syncthreads();
    if (half == 0) {
#pragma unroll
        for (int i = 0; i < IDB; i++) {
            float s = acc[i] + red[i][col];
            float s_hi = __shfl_down_sync(0xffffffff, s, 1);
            if (((col & 1) == 0) && i < nid)
                atomicAdd(reinterpret_cast<__half2*>(&g_Vh[(size_t)ids[i] * FF + col]),
                          __floats2half2_rn(s, s_hi));
        }
    }
}

// ---------------- histogram of destination (row) degrees ----------------
__global__ void hist_kernel(const int* __restrict__ ei) {
    int e = blockIdx.x * blockDim.x + threadIdx.x;
    if (e < EP) {
        int row = (e < EE) ? ei[e] : (e - EE);
        atomicAdd(&g_deg[row], 1);
    }
}

// ---------------- blocked scan, 2 kernels (scan2 merged into scan3) -------
__global__ void scan1_kernel() {           // per-block degree sums
    const int b = blockIdx.x;
    const int t = threadIdx.x;
    const int i = b * SB + t;
    int v = (i < NN) ? g_deg[i] : 0;
    __shared__ int ws[8];
#pragma unroll
    for (int o = 16; o > 0; o >>= 1) v += __shfl_down_sync(0xffffffff, v, o);
    if ((t & 31) == 0) ws[t >> 5] = v;
    __syncthreads();
    if (t < 8) {
        int s = ws[t];
#pragma unroll
        for (int o = 4; o > 0; o >>= 1) s += __shfl_down_sync(0xff, s, o);
        if (t == 0) g_bsum[b] = s;
    }
}

__global__ void scan23_kernel() {          // per-node offsets; reset g_deg
    const int b = blockIdx.x;
    const int t = threadIdx.x;
    __shared__ int sh[256];
    __shared__ int sboff;

    int bv = (t < NSB) ? g_bsum[t] : 0;
    sh[t] = bv;
    __syncthreads();
    for (int o = 1; o < 256; o <<= 1) {
        int u = (t >= o) ? sh[t - o] : 0;
        __syncthreads();
        sh[t] += u;
        __syncthreads();
    }
    if (t == 0) sboff = (b == 0) ? 0 : sh[b - 1];
    __syncthreads();

    const int i = b * SB + t;
    int v = (i < NN) ? g_deg[i] : 0;
    sh[t] = v;
    __syncthreads();
    for (int o = 1; o < 256; o <<= 1) {
        int u = (t >= o) ? sh[t - o] : 0;
        __syncthreads();
        sh[t] += u;
        __syncthreads();
    }
    const int excl = sh[t] - v + sboff;
    if (i < NN) {
        g_offs[i] = excl;
        g_cursor[i] = excl;
        g_deg[i] = 0;                      // reset for next replay
    }
    if (b == 0 && t == 0) g_offs[NN] = EP; // total is constant
}

// ---------------- scatter edges into destination-sorted order ----------------
__global__ void scatter_kernel(const int* __restrict__ ei) {
    int e = blockIdx.x * blockDim.x + threadIdx.x;
    if (e < EP) {
        int row, col;
        if (e < EE) { row = ei[e]; col = ei[EE + e]; }
        else        { row = e - EE; col = row; }
        int pos = atomicAdd(&g_cursor[row], 1);
        g_scol[pos] = col;
    }
}

// -------- aggregation: TWO warps per node (halve per-warp serial chain) -----
// Warp pair (2w, 2w+1) covers node n; each takes every other edge (stride 2).
// Per-edge body identical to the proven 1-warp version; partials combined via
// smem. Even warp writes the final row.
__global__ __launch_bounds__(256) void aggregate_kernel(
    const float* __restrict__ bias, float* __restrict__ out)
{
    const int wib  = threadIdx.x >> 5;          // warp in block: 0..7
    const int half = wib & 1;
    const int node = blockIdx.x * 4 + (wib >> 1);
    const int lane = threadIdx.x & 31;

    __shared__ float red[4][32][5];             // [node][lane][a0..a3,denom]

    float a0 = 0.f, a1 = 0.f, a2 = 0.f, a3 = 0.f;
    float denom = 0.f;

    if (node < NN) {
        uint2 qu = *reinterpret_cast<const uint2*>(&g_Qh[(size_t)node * FF + lane * 4]);
        const float2 q0 = __half22float2(*reinterpret_cast<__half2*>(&qu.x));
        const float2 q1 = __half22float2(*reinterpret_cast<__half2*>(&qu.y));

        const int s = g_offs[node];
        const int e = g_offs[node + 1];

        for (int p = s + half; p < e; p += 2) {
            const int c0 = g_scol[p];
            uint2 k0 = *reinterpret_cast<const uint2*>(&g_Kh[(size_t)c0 * FF + lane * 4]);
            uint2 v0 = *reinterpret_cast<const uint2*>(&g_Vh[(size_t)c0 * FF + lane * 4]);

            float2 ka = __half22float2(*reinterpret_cast<__half2*>(&k0.x));
            float2 kb = __half22float2(*reinterpret_cast<__half2*>(&k0.y));
            float d0 = q0.x * ka.x + q0.y * ka.y + q1.x * kb.x + q1.y * kb.y;
            d0 += __shfl_xor_sync(0xffffffff, d0, 1);
            d0 += __shfl_xor_sync(0xffffffff, d0, 2);
            const float w0 = __expf(d0 * 0.25f);

            float2 va = __half22float2(*reinterpret_cast<__half2*>(&v0.x));
            float2 vb = __half22float2(*reinterpret_cast<__half2*>(&v0.y));
            a0 = fmaf(w0, va.x, a0); a1 = fmaf(w0, va.y, a1);
            a2 = fmaf(w0, vb.x, a2); a3 = fmaf(w0, vb.y, a3);
            denom += w0;
        }
    }

    // odd warps deposit partials
    if (half == 1) {
        red[wib >> 1][lane][0] = a0;
        red[wib >> 1][lane][1] = a1;
        red[wib >> 1][lane][2] = a2;
        red[wib >> 1][lane][3] = a3;
        red[wib >> 1][lane][4] = denom;
    }
    __syncthreads();

    if (half == 0 && node < NN) {
        const int nn = wib >> 1;
        a0 += red[nn][lane][0];
        a1 += red[nn][lane][1];
        a2 += red[nn][lane][2];
        a3 += red[nn][lane][3];
        denom += red[nn][lane][4];

        const float inv = 1.f / denom;   // >= 1 edge guaranteed (self loop)
        const float4 b = *reinterpret_cast<const float4*>(&bias[lane * 4]);
        float4 o;
        o.x = fmaf(a0, inv, b.x);
        o.y = fmaf(a1, inv, b.y);
        o.z = fmaf(a2, inv, b.z);
        o.w = fmaf(a3, inv, b.w);
        *reinterpret_cast<float4*>(&out[(size_t)node * FF + lane * 4]) = o;
    }
}

// ---------------- launch ----------------
extern "C" void kernel_launch(void* const* d_in, const int* in_sizes, int n_in,
                              void* d_out, int out_size)
{
    const float* x    = (const float*)d_in[0];
    const int*   ei   = (const int*)d_in[1];     // JAX x64 disabled -> int32
    const int*   idix = (const int*)d_in[2];
    const float* Wq   = (const float*)d_in[3];
    const float* bq   = (const float*)d_in[4];
    const float* Wk   = (const float*)d_in[5];
    const float* bk   = (const float*)d_in[6];
    const float* Wv   = (const float*)d_in[7];
    const float* Wid  = (const float*)d_in[8];
    const float* bo   = (const float*)d_in[9];
    float* out = (float*)d_out;

    static cudaStream_t s2 = nullptr;
    static cudaEvent_t evA = nullptr, evB = nullptr;
    static bool init_done = false;
    if (!init_done) {
        cudaFuncSetAttribute(gemm3_kernel,
                             cudaFuncAttributeMaxDynamicSharedMemorySize, GEMM_SMEM);
        cudaStreamCreateWithFlags(&s2, cudaStreamNonBlocking);
        cudaEventCreateWithFlags(&evA, cudaEventDisableTiming);
        cudaEventCreateWithFlags(&evB, cudaEventDisableTiming);
        init_done = true;
    }

    // fork: sort chain hides under prep+GEMMs; join before aggregate.
    // Enqueue order keeps gemm3 as kernel #4 (ncu profiles #4).
    cudaEventRecord(evA, 0);
    cudaStreamWaitEvent(s2, evA, 0);

    prep_kernel<<<XB + 192, 256>>>(x, Wq, Wk, Wv);                    // #1 (s0)
    hist_kernel<<<(EP + 255) / 256, 256, 0, s2>>>(ei);                // #2 (s2)
    scan1_kernel<<<NSB, SB, 0, s2>>>();                               // #3 (s2)
    dim3 ggrid((NN + 127) / 128, 3);
    gemm3_kernel<<<ggrid, 256, GEMM_SMEM>>>(bq, bk);                  // #4 (s0)
    scan23_kernel<<<NSB, SB, 0, s2>>>();                              // #5 (s2)
    scatter_kernel<<<(EP + 255) / 256, 256, 0, s2>>>(ei);             // #6 (s2)
    idgemm_kernel<<<(NID + IDB - 1) / IDB, 256>>>(x, idix, Wid);      // #7 (s0)

    cudaEventRecord(evB, s2);
    cudaStreamWaitEvent(0, evB, 0);

    // fused attention softmax + aggregation, two warps per node
    aggregate_kernel<<<(NN + 3) / 4, 256>>>(bo, out);                 // #8 (s0)
}

// round 16
// speedup vs baseline: 1.1544x; 1.1544x over previous
#include <cuda_runtime.h>
#include <cuda_fp16.h>
#include <math.h>

#define NN      50000   // nodes
#define FF      128     // features
#define EE      600000  // edges (before self loops)
#define EP      (EE + NN)
#define NID     5000
#define SB      256
#define NSB     ((NN + SB - 1) / SB)   // 196
// dh = 16, scale = 0.25

// ---------------- device scratch (static; no allocations) ----------------
__device__ __half g_Qh[NN * FF];
__device__ __half g_Kh[NN * FF];
__device__ __half g_Vh[NN * FF];
__device__ __half g_Xh[NN * FF];          // x pre-converted to fp16
__device__ __half g_Wh[3 * FF * FF];      // Wq/Wk/Wv transposed to [n][k] fp16
__device__ int    g_deg[NN];      // zero-initialized at load; scan23 re-zeros it
__device__ int    g_offs[NN + 1];
__device__ int    g_cursor[NN];
__device__ int    g_scol[EP];
__device__ int    g_bsum[NSB];

// ---------------- helpers ----------------
__device__ __forceinline__ void mma_f16(float* c, const unsigned* a, const unsigned* b) {
    asm volatile(
        "mma.sync.aligned.m16n8k16.row.col.f32.f16.f16.f32 "
        "{%0,%1,%2,%3},{%4,%5,%6,%7},{%8,%9},{%0,%1,%2,%3};"
        : "+f"(c[0]), "+f"(c[1]), "+f"(c[2]), "+f"(c[3])
        : "r"(a[0]), "r"(a[1]), "r"(a[2]), "r"(a[3]), "r"(b[0]), "r"(b[1]));
}

__device__ __forceinline__ void cp_async16(void* dst_smem, const void* src) {
    unsigned d = (unsigned)__cvta_generic_to_shared(dst_smem);
    asm volatile("cp.async.cg.shared.global [%0], [%1], 16;" :: "r"(d), "l"(src));
}
__device__ __forceinline__ void cp_commit() {
    asm volatile("cp.async.commit_group;");
}
template <int N>
__device__ __forceinline__ void cp_wait() {
    asm volatile("cp.async.wait_group %0;" :: "n"(N));
}

// ------- combined prep (x->fp16, W->fp16 [n][k]) + degree histogram --------
#define XB 6250                            // blocks for x (6.4M/4/256)
#define WB 192                             // blocks for W (3*16384/256)
#define HB ((EP + 255) / 256)              // blocks for hist (2540)
__global__ void prep_hist_kernel(const float* __restrict__ x,
                                 const float* __restrict__ Wq,
                                 const float* __restrict__ Wk,
                                 const float* __restrict__ Wv,
                                 const int* __restrict__ ei)
{
    const int b = blockIdx.x;
    if (b < XB) {
        const int i4 = (b * 256 + threadIdx.x) * 4;
        float4 v = *reinterpret_cast<const float4*>(&x[i4]);
        *reinterpret_cast<__half2*>(&g_Xh[i4])     = __floats2half2_rn(v.x, v.y);
        *reinterpret_cast<__half2*>(&g_Xh[i4 + 2]) = __floats2half2_rn(v.z, v.w);
    } else if (b < XB + WB) {
        const int idx = (b - XB) * 256 + threadIdx.x;   // 0..49151
        const int m = idx >> 14;
        const int rem = idx & 16383;
        const int k = rem >> 7, n = rem & 127;
        const float* W = (m == 0) ? Wq : (m == 1) ? Wk : Wv;
        g_Wh[m * 16384 + n * 128 + k] = __float2half(W[k * 128 + n]);
    } else {
        const int e = (b - XB - WB) * 256 + threadIdx.x;
        if (e < EP) {
            int row = (e < EE) ? ei[e] : (e - EE);
            atomicAdd(&g_deg[row], 1);
        }
    }
}

// ---------------- fp16 QKV GEMM, 3-stage cp.async pipeline -----------------
// blockIdx.y: 0->Q(relu+bias), 1->K(relu+bias), 2->V(plain)
#define KC 32
#define HS 40                              // halves per smem row (32 + 8 pad)
#define CHUNK_H (128 * HS)                 // halves per A or B chunk
#define GEMM_SMEM (3 * 2 * CHUNK_H * 2)    // 3 stages x (A+B) x 2B = 61440

__global__ __launch_bounds__(256, 2) void gemm3_kernel(
    const float* __restrict__ bq, const float* __restrict__ bk)
{
    const int which = blockIdx.y;
    const float* bias = (which == 0) ? bq : (which == 1) ? bk : nullptr;
    __half* out = (which == 0) ? g_Qh : (which == 1) ? g_Kh : g_Vh;
    const __half* Wh = g_Wh + which * 16384;

    extern __shared__ __half hsmem[];

    const int tid  = threadIdx.x;
    const int lane = tid & 31;
    const int warp = tid >> 5;
    const int wm   = warp >> 1;
    const int wn   = warp & 1;
    const int rowBase = blockIdx.x * 128;

    const int g0   = tid * 2;                  // even
    const int row  = g0 >> 2;                  // same row for both granules
    const int c8a  = (g0 & 3) * 8;             // halves offset of granule 0
    const int c8b  = ((g0 + 1) & 3) * 8;       // granule 1
    const int gRow = min(rowBase + row, NN - 1);

    auto prefetch = [&](int c) {
        const int kc = c * KC;
        __half* As = hsmem + (c % 3) * 2 * CHUNK_H;
        __half* Bs = As + CHUNK_H;
        cp_async16(&As[row * HS + c8a], &g_Xh[(size_t)gRow * FF + kc + c8a]);
        cp_async16(&As[row * HS + c8b], &g_Xh[(size_t)gRow * FF + kc + c8b]);
        cp_async16(&Bs[row * HS + c8a], &Wh[(size_t)row * FF + kc + c8a]);
        cp_async16(&Bs[row * HS + c8b], &Wh[(size_t)row * FF + kc + c8b]);
        cp_commit();
    };

    float acc[2][8][4];
#pragma unroll
    for (int i = 0; i < 2; i++)
#pragma unroll
        for (int j = 0; j < 8; j++)
#pragma unroll
            for (int t = 0; t < 4; t++) acc[i][j][t] = 0.f;

    const int lq = lane >> 2;
    const int lr = lane & 3;

    prefetch(0);
    prefetch(1);

    for (int c = 0; c < 4; c++) {
        if (c + 2 < 4) { prefetch(c + 2); cp_wait<2>(); }
        else if (c + 1 < 4) cp_wait<1>();
        else cp_wait<0>();
        __syncthreads();

        const __half* Ab = hsmem + (c % 3) * 2 * CHUNK_H;
        const __half* Bb = Ab + CHUNK_H;
#pragma unroll
        for (int kk = 0; kk < 2; kk++) {
            const int bk16 = kk * 16 + 2 * lr;
            unsigned bf[8][2];
#pragma unroll
            for (int j = 0; j < 8; j++) {
                int n = wn * 64 + j * 8 + lq;
                bf[j][0] = *reinterpret_cast<const unsigned*>(&Bb[n * HS + bk16]);
                bf[j][1] = *reinterpret_cast<const unsigned*>(&Bb[n * HS + bk16 + 8]);
            }
            unsigned af[2][4];
#pragma unroll
            for (int i = 0; i < 2; i++) {
                int r0 = wm * 32 + i * 16 + lq;
                af[i][0] = *reinterpret_cast<const unsigned*>(&Ab[r0 * HS + bk16]);
                af[i][1] = *reinterpret_cast<const unsigned*>(&Ab[(r0 + 8) * HS + bk16]);
                af[i][2] = *reinterpret_cast<const unsigned*>(&Ab[r0 * HS + bk16 + 8]);
                af[i][3] = *reinterpret_cast<const unsigned*>(&Ab[(r0 + 8) * HS + bk16 + 8]);
            }
#pragma unroll
            for (int i = 0; i < 2; i++)
#pragma unroll
                for (int j = 0; j < 8; j++)
                    mma_f16(acc[i][j], af[i], bf[j]);
        }
        __syncthreads();
    }

    // ---- epilogue: bias (+relu) -> half2 store ----
#pragma unroll
    for (int i = 0; i < 2; i++) {
#pragma unroll
        for (int j = 0; j < 8; j++) {
            int col = wn * 64 + j * 8 + lr * 2;
            float b0 = 0.f, b1 = 0.f;
            if (which < 2) { b0 = bias[col]; b1 = bias[col + 1]; }
            int r0 = rowBase + wm * 32 + i * 16 + lq;
            int r1 = r0 + 8;
            float v00 = acc[i][j][0] + b0, v01 = acc[i][j][1] + b1;
            float v10 = acc[i][j][2] + b0, v11 = acc[i][j][3] + b1;
            if (which < 2) {
                v00 = fmaxf(v00, 0.f); v01 = fmaxf(v01, 0.f);
                v10 = fmaxf(v10, 0.f); v11 = fmaxf(v11, 0.f);
            }
            if (r0 < NN)
                *reinterpret_cast<__half2*>(&out[(size_t)r0 * FF + col]) =
                    __floats2half2_rn(v00, v01);
            if (r1 < NN)
                *reinterpret_cast<__half2*>(&out[(size_t)r1 * FF + col]) =
                    __floats2half2_rn(v10, v11);
        }
    }
}

// -------- id scatter GEMM: V[id] += x[id] @ kernel_id --------
#define IDB 16
__global__ __launch_bounds__(256) void idgemm_kernel(
    const float* __restrict__ x,
    const int* __restrict__ id_index,
    const float* __restrict__ Wid)
{
    __shared__ float xs[IDB][FF];
    __shared__ float red[IDB][FF];
    __shared__ int ids[IDB];

    const int tid = threadIdx.x;
    const int base = blockIdx.x * IDB;
    const int nid = min(IDB, NID - base);

    if (tid < nid) ids[tid] = id_index[base + tid];
    __syncthreads();

    for (int i = tid; i < IDB * FF; i += 256) {
        int r = i >> 7;
        if (r < nid) xs[r][i & 127] = x[(size_t)ids[r] * FF + (i & 127)];
    }
    __syncthreads();

    const int col = tid & 127;
    const int half = tid >> 7;
    float acc[IDB];
#pragma unroll
    for (int i = 0; i < IDB; i++) acc[i] = 0.f;

    const int k0 = half * 64;
#pragma unroll 4
    for (int k = k0; k < k0 + 64; k++) {
        const float w = Wid[k * FF + col];
#pragma unroll
        for (int i = 0; i < IDB; i++)
            acc[i] = fmaf(xs[i][k], w, acc[i]);
    }

    if (half == 1) {
#pragma unroll
        for (int i = 0; i < IDB; i++) red[i][col] = acc[i];
    }
    __syncthreads();
    if (half == 0) {
#pragma unroll
        for (int i = 0; i < IDB; i++) {
            float s = acc[i] + red[i][col];
            float s_hi = __shfl_down_sync(0xffffffff, s, 1);
            if (((col & 1) == 0) && i < nid)
                atomicAdd(reinterpret_cast<__half2*>(&g_Vh[(size_t)ids[i] * FF + col]),
                          __floats2half2_rn(s, s_hi));
        }
    }
}

// ---------------- blocked scan, 2 kernels -----------------
__global__ void scan1_kernel() {           // per-block degree sums
    const int b = blockIdx.x;
    const int t = threadIdx.x;
    const int i = b * SB + t;
    int v = (i < NN) ? g_deg[i] : 0;
    __shared__ int ws[8];
#pragma unroll
    for (int o = 16; o > 0; o >>= 1) v += __shfl_down_sync(0xffffffff, v, o);
    if ((t & 31) == 0) ws[t >> 5] = v;
    __syncthreads();
    if (t < 8) {
        int s = ws[t];
#pragma unroll
        for (int o = 4; o > 0; o >>= 1) s += __shfl_down_sync(0xff, s, o);
        if (t == 0) g_bsum[b] = s;
    }
}

__global__ void scan23_kernel() {          // per-node offsets; reset g_deg
    const int b = blockIdx.x;
    const int t = threadIdx.x;
    __shared__ int sh[256];
    __shared__ int sboff;

    int bv = (t < NSB) ? g_bsum[t] : 0;
    sh[t] = bv;
    __syncthreads();
    for (int o = 1; o < 256; o <<= 1) {
        int u = (t >= o) ? sh[t - o] : 0;
        __syncthreads();
        sh[t] += u;
        __syncthreads();
    }
    if (t == 0) sboff = (b == 0) ? 0 : sh[b - 1];
    __syncthreads();

    const int i = b * SB + t;
    int v = (i < NN) ? g_deg[i] : 0;
    sh[t] = v;
    __syncthreads();
    for (int o = 1; o < 256; o <<= 1) {
        int u = (t >= o) ? sh[t - o] : 0;
        __syncthreads();
        sh[t] += u;
        __syncthreads();
    }
    const int excl = sh[t] - v + sboff;
    if (i < NN) {
        g_offs[i] = excl;
        g_cursor[i] = excl;
        g_deg[i] = 0;                      // reset for next replay
    }
    if (b == 0 && t == 0) g_offs[NN] = EP; // total is constant
}

// ---------------- scatter edges into destination-sorted order ----------------
__global__ void scatter_kernel(const int* __restrict__ ei) {
    int e = blockIdx.x * blockDim.x + threadIdx.x;
    if (e < EP) {
        int row, col;
        if (e < EE) { row = ei[e]; col = ei[EE + e]; }
        else        { row = e - EE; col = row; }
        int pos = atomicAdd(&g_cursor[row], 1);
        g_scol[pos] = col;
    }
}

// -------- per-node attention aggregation (one warp per node, fp16 gathers) ---
// 2x unrolled edge loop, uint2 per lane. LOCKED: L2-throughput bound (333MB);
// 4x unroll, half-warp-per-edge, and 2-warp-per-node all measured worse.
__global__ __launch_bounds__(256) void aggregate_kernel(
    const float* __restrict__ bias, float* __restrict__ out)
{
    const int n = (blockIdx.x * blockDim.x + threadIdx.x) >> 5;
    const int lane = threadIdx.x & 31;
    if (n >= NN) return;

    uint2 qu = *reinterpret_cast<const uint2*>(&g_Qh[(size_t)n * FF + lane * 4]);
    const float2 q0 = __half22float2(*reinterpret_cast<__half2*>(&qu.x));
    const float2 q1 = __half22float2(*reinterpret_cast<__half2*>(&qu.y));

    float a0 = 0.f, a1 = 0.f, a2 = 0.f, a3 = 0.f;
    float denom = 0.f;

    const int s = g_offs[n];
    const int e = g_offs[n + 1];
    int p = s;

    for (; p + 2 <= e; p += 2) {
        const int c0 = g_scol[p];
        const int c1 = g_scol[p + 1];
        uint2 k0 = *reinterpret_cast<const uint2*>(&g_Kh[(size_t)c0 * FF + lane * 4]);
        uint2 k1 = *reinterpret_cast<const uint2*>(&g_Kh[(size_t)c1 * FF + lane * 4]);
        uint2 v0 = *reinterpret_cast<const uint2*>(&g_Vh[(size_t)c0 * FF + lane * 4]);
        uint2 v1 = *reinterpret_cast<const uint2*>(&g_Vh[(size_t)c1 * FF + lane * 4]);

        float2 ka = __half22float2(*reinterpret_cast<__half2*>(&k0.x));
        float2 kb = __half22float2(*reinterpret_cast<__half2*>(&k0.y));
        float d0 = q0.x * ka.x + q0.y * ka.y + q1.x * kb.x + q1.y * kb.y;
        ka = __half22float2(*reinterpret_cast<__half2*>(&k1.x));
        kb = __half22float2(*reinterpret_cast<__half2*>(&k1.y));
        float d1 = q0.x * ka.x + q0.y * ka.y + q1.x * kb.x + q1.y * kb.y;

        d0 += __shfl_xor_sync(0xffffffff, d0, 1);
        d1 += __shfl_xor_sync(0xffffffff, d1, 1);
        d0 += __shfl_xor_sync(0xffffffff, d0, 2);
        d1 += __shfl_xor_sync(0xffffffff, d1, 2);

        const float w0 = __expf(d0 * 0.25f);
        const float w1 = __expf(d1 * 0.25f);

        float2 va = __half22float2(*reinterpret_cast<__half2*>(&v0.x));
        float2 vb = __half22float2(*reinterpret_cast<__half2*>(&v0.y));
        a0 = fmaf(w0, va.x, a0); a1 = fmaf(w0, va.y, a1);
        a2 = fmaf(w0, vb.x, a2); a3 = fmaf(w0, vb.y, a3);
        va = __half22float2(*reinterpret_cast<__half2*>(&v1.x));
        vb = __half22float2(*reinterpret_cast<__half2*>(&v1.y));
        a0 = fmaf(w1, va.x, a0); a1 = fmaf(w1, va.y, a1);
        a2 = fmaf(w1, vb.x, a2); a3 = fmaf(w1, vb.y, a3);
        denom += w0 + w1;
    }
    for (; p < e; p++) {
        const int c0 = g_scol[p];
        uint2 k0 = *reinterpret_cast<const uint2*>(&g_Kh[(size_t)c0 * FF + lane * 4]);
        float2 ka = __half22float2(*reinterpret_cast<__half2*>(&k0.x));
        float2 kb = __half22float2(*reinterpret_cast<__half2*>(&k0.y));
        float d0 = q0.x * ka.x + q0.y * ka.y + q1.x * kb.x + q1.y * kb.y;
        d0 += __shfl_xor_sync(0xffffffff, d0, 1);
        d0 += __shfl_xor_sync(0xffffffff, d0, 2);
        const float w0 = __expf(d0 * 0.25f);
        uint2 v0 = *reinterpret_cast<const uint2*>(&g_Vh[(size_t)c0 * FF + lane * 4]);
        float2 va = __half22float2(*reinterpret_cast<__half2*>(&v0.x));
        float2 vb = __half22float2(*reinterpret_cast<__half2*>(&v0.y));
        a0 = fmaf(w0, va.x, a0); a1 = fmaf(w0, va.y, a1);
        a2 = fmaf(w0, vb.x, a2); a3 = fmaf(w0, vb.y, a3);
        denom += w0;
    }

    const float inv = 1.f / denom;   // >= 1 edge guaranteed (self loop)
    const float4 b = *reinterpret_cast<const float4*>(&bias[lane * 4]);
    float4 o;
    o.x = fmaf(a0, inv, b.x);
    o.y = fmaf(a1, inv, b.y);
    o.z = fmaf(a2, inv, b.z);
    o.w = fmaf(a3, inv, b.w);
    *reinterpret_cast<float4*>(&out[(size_t)n * FF + lane * 4]) = o;
}

// ---------------- launch ----------------
extern "C" void kernel_launch(void* const* d_in, const int* in_sizes, int n_in,
                              void* d_out, int out_size)
{
    const float* x    = (const float*)d_in[0];
    const int*   ei   = (const int*)d_in[1];     // JAX x64 disabled -> int32
    const int*   idix = (const int*)d_in[2];
    const float* Wq   = (const float*)d_in[3];
    const float* bq   = (const float*)d_in[4];
    const float* Wk   = (const float*)d_in[5];
    const float* bk   = (const float*)d_in[6];
    const float* Wv   = (const float*)d_in[7];
    const float* Wid  = (const float*)d_in[8];
    const float* bo   = (const float*)d_in[9];
    float* out = (float*)d_out;

    static cudaStream_t s2 = nullptr;
    static cudaEvent_t evA = nullptr, evB = nullptr;
    static bool init_done = false;
    if (!init_done) {
        cudaFuncSetAttribute(gemm3_kernel,
                             cudaFuncAttributeMaxDynamicSharedMemorySize, GEMM_SMEM);
        cudaStreamCreateWithFlags(&s2, cudaStreamNonBlocking);
        cudaEventCreateWithFlags(&evA, cudaEventDisableTiming);
        cudaEventCreateWithFlags(&evB, cudaEventDisableTiming);
        init_done = true;
    }

    // prep+hist fused on s0; scan chain forks to s2 (hides under gemm);
    // join before aggregate. gemm3 stays kernel #4 for ncu continuity.
    prep_hist_kernel<<<XB + WB + HB, 256>>>(x, Wq, Wk, Wv, ei);       // #1 (s0)
    cudaEventRecord(evA, 0);
    cudaStreamWaitEvent(s2, evA, 0);

    scan1_kernel<<<NSB, SB, 0, s2>>>();                               // #2 (s2)
    scan23_kernel<<<NSB, SB, 0, s2>>>();                              // #3 (s2)
    dim3 ggrid((NN + 127) / 128, 3);
    gemm3_kernel<<<ggrid, 256, GEMM_SMEM>>>(bq, bk);                  // #4 (s0)
    scatter_kernel<<<(EP + 255) / 256, 256, 0, s2>>>(ei);             // #5 (s2)
    idgemm_kernel<<<(NID + IDB - 1) / IDB, 256>>>(x, idix, Wid);      // #6 (s0)

    cudaEventRecord(evB, s2);
    cudaStreamWaitEvent(0, evB, 0);

    // fused attention softmax + aggregation, one warp per node
    aggregate_kernel<<<(NN * 32 + 255) / 256, 256>>>(bo, out);        // #7 (s0)
}

// round 17
// speedup vs baseline: 1.1569x; 1.0021x over previous
#include <cuda_runtime.h>
#include <cuda_fp16.h>
#include <math.h>

#define NN      50000   // nodes
#define FF      128     // features
#define EE      600000  // edges (before self loops)
#define EP      (EE + NN)
#define NID     5000
#define SB      256
#define NSB     ((NN + SB - 1) / SB)   // 196
// dh = 16, scale = 0.25

// ---------------- device scratch (static; no allocations) ----------------
__device__ __half g_Qh[NN * FF];
__device__ __half g_Kh[NN * FF];
__device__ __half g_Vh[NN * FF];
__device__ __half g_Xh[NN * FF];          // x pre-converted to fp16
__device__ __half g_Wh[3 * FF * FF];      // Wq/Wk/Wv transposed to [n][k] fp16
__device__ int    g_deg[NN];      // zero-initialized at load; scan23 re-zeros it
__device__ int    g_offs[NN + 1];
__device__ int    g_cursor[NN];
__device__ int    g_scol[EP];
__device__ int    g_bsum[NSB];

// ---------------- helpers ----------------
__device__ __forceinline__ void mma_f16(float* c, const unsigned* a, const unsigned* b) {
    asm volatile(
        "mma.sync.aligned.m16n8k16.row.col.f32.f16.f16.f32 "
        "{%0,%1,%2,%3},{%4,%5,%6,%7},{%8,%9},{%0,%1,%2,%3};"
        : "+f"(c[0]), "+f"(c[1]), "+f"(c[2]), "+f"(c[3])
        : "r"(a[0]), "r"(a[1]), "r"(a[2]), "r"(a[3]), "r"(b[0]), "r"(b[1]));
}

__device__ __forceinline__ void ldsm4(unsigned& r0, unsigned& r1,
                                      unsigned& r2, unsigned& r3, unsigned addr) {
    asm volatile("ldmatrix.sync.aligned.m8n8.x4.shared.b16 {%0,%1,%2,%3}, [%4];"
                 : "=r"(r0), "=r"(r1), "=r"(r2), "=r"(r3) : "r"(addr));
}

__device__ __forceinline__ void cp_async16(void* dst_smem, const void* src) {
    unsigned d = (unsigned)__cvta_generic_to_shared(dst_smem);
    asm volatile("cp.async.cg.shared.global [%0], [%1], 16;" :: "r"(d), "l"(src));
}
__device__ __forceinline__ void cp_commit() {
    asm volatile("cp.async.commit_group;");
}
template <int N>
__device__ __forceinline__ void cp_wait() {
    asm volatile("cp.async.wait_group %0;" :: "n"(N));
}

// ------- combined prep (x->fp16, W->fp16 [n][k]) + degree histogram --------
#define XB 6250                            // blocks for x (6.4M/4/256)
#define WB 192                             // blocks for W (3*16384/256)
#define HB ((EP + 255) / 256)              // blocks for hist (2540)
__global__ void prep_hist_kernel(const float* __restrict__ x,
                                 const float* __restrict__ Wq,
                                 const float* __restrict__ Wk,
                                 const float* __restrict__ Wv,
                                 const int* __restrict__ ei)
{
    const int b = blockIdx.x;
    if (b < XB) {
        const int i4 = (b * 256 + threadIdx.x) * 4;
        float4 v = *reinterpret_cast<const float4*>(&x[i4]);
        *reinterpret_cast<__half2*>(&g_Xh[i4])     = __floats2half2_rn(v.x, v.y);
        *reinterpret_cast<__half2*>(&g_Xh[i4 + 2]) = __floats2half2_rn(v.z, v.w);
    } else if (b < XB + WB) {
        const int idx = (b - XB) * 256 + threadIdx.x;   // 0..49151
        const int m = idx >> 14;
        const int rem = idx & 16383;
        const int k = rem >> 7, n = rem & 127;
        const float* W = (m == 0) ? Wq : (m == 1) ? Wk : Wv;
        g_Wh[m * 16384 + n * 128 + k] = __float2half(W[k * 128 + n]);
    } else {
        const int e = (b - XB - WB) * 256 + threadIdx.x;
        if (e < EP) {
            int row = (e < EE) ? ei[e] : (e - EE);
            atomicAdd(&g_deg[row], 1);
        }
    }
}

// ---------------- fp16 QKV GEMM, 3-stage cp.async + ldmatrix ---------------
// blockIdx.y: 0->Q(relu+bias), 1->K(relu+bias), 2->V(plain)
#define KC 32
#define HS 40                              // halves per smem row (32 + 8 pad)
#define CHUNK_H (128 * HS)                 // halves per A or B chunk
#define GEMM_SMEM (3 * 2 * CHUNK_H * 2)    // 3 stages x (A+B) x 2B = 61440

__global__ __launch_bounds__(256, 2) void gemm3_kernel(
    const float* __restrict__ bq, const float* __restrict__ bk)
{
    const int which = blockIdx.y;
    const float* bias = (which == 0) ? bq : (which == 1) ? bk : nullptr;
    __half* out = (which == 0) ? g_Qh : (which == 1) ? g_Kh : g_Vh;
    const __half* Wh = g_Wh + which * 16384;

    extern __shared__ __half hsmem[];
    const unsigned smem_u32 = (unsigned)__cvta_generic_to_shared(hsmem);

    const int tid  = threadIdx.x;
    const int lane = tid & 31;
    const int warp = tid >> 5;
    const int wm   = warp >> 1;
    const int wn   = warp & 1;
    const int rowBase = blockIdx.x * 128;

    const int g0   = tid * 2;                  // even
    const int row  = g0 >> 2;                  // same row for both granules
    const int c8a  = (g0 & 3) * 8;             // halves offset of granule 0
    const int c8b  = ((g0 + 1) & 3) * 8;       // granule 1
    const int gRow = min(rowBase + row, NN - 1);

    auto prefetch = [&](int c) {
        const int kc = c * KC;
        __half* As = hsmem + (c % 3) * 2 * CHUNK_H;
        __half* Bs = As + CHUNK_H;
        cp_async16(&As[row * HS + c8a], &g_Xh[(size_t)gRow * FF + kc + c8a]);
        cp_async16(&As[row * HS + c8b], &g_Xh[(size_t)gRow * FF + kc + c8b]);
        cp_async16(&Bs[row * HS + c8a], &Wh[(size_t)row * FF + kc + c8a]);
        cp_async16(&Bs[row * HS + c8b], &Wh[(size_t)row * FF + kc + c8b]);
        cp_commit();
    };

    float acc[2][8][4];
#pragma unroll
    for (int i = 0; i < 2; i++)
#pragma unroll
        for (int j = 0; j < 8; j++)
#pragma unroll
            for (int t = 0; t < 4; t++) acc[i][j][t] = 0.f;

    const int lq = lane >> 2;
    const int lr = lane & 3;
    const int sub = lane & 7;                  // row within 8x8 matrix
    const int grp = lane >> 3;                 // which of 4 matrices

    // ldmatrix address offsets (in halves), fixed per thread:
    // A: matrices (r,k0)/(r+8,k0)/(r,k8)/(r+8,k8) -> rowoff=(grp&1)*8, koff=(grp>>1)*8
    const int aRowOff = (grp & 1) * 8 + sub;
    const int aKOff   = (grp >> 1) * 8;
    // B: matrices (n0,k0)/(n0,k8)/(n8,k0)/(n8,k8) -> noff=(grp>>1)*8, koff=(grp&1)*8
    const int bNOff   = (grp >> 1) * 8 + sub;
    const int bKOff   = (grp & 1) * 8;

    prefetch(0);
    prefetch(1);

    for (int c = 0; c < 4; c++) {
        if (c + 2 < 4) { prefetch(c + 2); cp_wait<2>(); }
        else if (c + 1 < 4) cp_wait<1>();
        else cp_wait<0>();
        __syncthreads();

        const unsigned Abase = smem_u32 + (unsigned)((c % 3) * 2 * CHUNK_H) * 2u;
        const unsigned Bbase = Abase + (unsigned)CHUNK_H * 2u;
#pragma unroll
        for (int kk = 0; kk < 2; kk++) {
            const int kb = kk * 16;
            unsigned af[2][4];
#pragma unroll
            for (int i = 0; i < 2; i++) {
                const int r = wm * 32 + i * 16 + aRowOff;
                ldsm4(af[i][0], af[i][1], af[i][2], af[i][3],
                      Abase + (unsigned)(r * HS + kb + aKOff) * 2u);
            }
            unsigned bf[8][2];
#pragma unroll
            for (int jj = 0; jj < 4; jj++) {
                const int n = wn * 64 + jj * 16 + bNOff;
                ldsm4(bf[2 * jj][0], bf[2 * jj][1], bf[2 * jj + 1][0], bf[2 * jj + 1][1],
                      Bbase + (unsigned)(n * HS + kb + bKOff) * 2u);
            }
#pragma unroll
            for (int i = 0; i < 2; i++)
#pragma unroll
                for (int j = 0; j < 8; j++)
                    mma_f16(acc[i][j], af[i], bf[j]);
        }
        __syncthreads();
    }

    // ---- epilogue: bias (+relu) -> half2 store ----
#pragma unroll
    for (int i = 0; i < 2; i++) {
#pragma unroll
        for (int j = 0; j < 8; j++) {
            int col = wn * 64 + j * 8 + lr * 2;
            float b0 = 0.f, b1 = 0.f;
            if (which < 2) { b0 = bias[col]; b1 = bias[col + 1]; }
            int r0 = rowBase + wm * 32 + i * 16 + lq;
            int r1 = r0 + 8;
            float v00 = acc[i][j][0] + b0, v01 = acc[i][j][1] + b1;
            float v10 = acc[i][j][2] + b0, v11 = acc[i][j][3] + b1;
            if (which < 2) {
                v00 = fmaxf(v00, 0.f); v01 = fmaxf(v01, 0.f);
                v10 = fmaxf(v10, 0.f); v11 = fmaxf(v11, 0.f);
            }
            if (r0 < NN)
                *reinterpret_cast<__half2*>(&out[(size_t)r0 * FF + col]) =
                    __floats2half2_rn(v00, v01);
            if (r1 < NN)
                *reinterpret_cast<__half2*>(&out[(size_t)r1 * FF + col]) =
                    __floats2half2_rn(v10, v11);
        }
    }
}

// -------- id scatter GEMM: V[id] += x[id] @ kernel_id --------
#define IDB 16
__global__ __launch_bounds__(256) void idgemm_kernel(
    const float* __restrict__ x,
    const int* __restrict__ id_index,
    const float* __restrict__ Wid)
{
    __shared__ float xs[IDB][FF];
    __shared__ float red[IDB][FF];
    __shared__ int ids[IDB];

    const int tid = threadIdx.x;
    const int base = blockIdx.x * IDB;
    const int nid = min(IDB, NID - base);

    if (tid < nid) ids[tid] = id_index[base + tid];
    __syncthreads();

    for (int i = tid; i < IDB * FF; i += 256) {
        int r = i >> 7;
        if (r < nid) xs[r][i & 127] = x[(size_t)ids[r] * FF + (i & 127)];
    }
    __syncthreads();

    const int col = tid & 127;
    const int half = tid >> 7;
    float acc[IDB];
#pragma unroll
    for (int i = 0; i < IDB; i++) acc[i] = 0.f;

    const int k0 = half * 64;
#pragma unroll 4
    for (int k = k0; k < k0 + 64; k++) {
        const float w = Wid[k * FF + col];
#pragma unroll
        for (int i = 0; i < IDB; i++)
            acc[i] = fmaf(xs[i][k], w, acc[i]);
    }

    if (half == 1) {
#pragma unroll
        for (int i = 0; i < IDB; i++) red[i][col] = acc[i];
    }
    __syncthreads();
    if (half == 0) {
#pragma unroll
        for (int i = 0; i < IDB; i++) {
            float s = acc[i] + red[i][col];
            float s_hi = __shfl_down_sync(0xffffffff, s, 1);
            if (((col & 1) == 0) && i < nid)
                atomicAdd(reinterpret_cast<__half2*>(&g_Vh[(size_t)ids[i] * FF + col]),
                          __floats2half2_rn(s, s_hi));
        }
    }
}

// ---------------- blocked scan, 2 kernels -----------------
__global__ void scan1_kernel() {           // per-block degree sums
    const int b = blockIdx.x;
    const int t = threadIdx.x;
    const int i = b * SB + t;
    int v = (i < NN) ? g_deg[i] : 0;
    __shared__ int ws[8];
#pragma unroll
    for (int o = 16; o > 0; o >>= 1) v += __shfl_down_sync(0xffffffff, v, o);
    if ((t & 31) == 0) ws[t >> 5] = v;
    __syncthreads();
    if (t < 8) {
        int s = ws[t];
#pragma unroll
        for (int o = 4; o > 0; o >>= 1) s += __shfl_down_sync(0xff, s, o);
        if (t == 0) g_bsum[b] = s;
    }
}

__global__ void scan23_kernel() {          // per-node offsets; reset g_deg
    const int b = blockIdx.x;
    const int t = threadIdx.x;
    __shared__ int sh[256];
    __shared__ int sboff;

    int bv = (t < NSB) ? g_bsum[t] : 0;
    sh[t] = bv;
    __syncthreads();
    for (int o = 1; o < 256; o <<= 1) {
        int u = (t >= o) ? sh[t - o] : 0;
        __syncthreads();
        sh[t] += u;
        __syncthreads();
    }
    if (t == 0) sboff = (b == 0) ? 0 : sh[b - 1];
    __syncthreads();

    const int i = b * SB + t;
    int v = (i < NN) ? g_deg[i] : 0;
    sh[t] = v;
    __syncthreads();
    for (int o = 1; o < 256; o <<= 1) {
        int u = (t >= o) ? sh[t - o] : 0;
        __syncthreads();
        sh[t] += u;
        __syncthreads();
    }
    const int excl = sh[t] - v + sboff;
    if (i < NN) {
        g_offs[i] = excl;
        g_cursor[i] = excl;
        g_deg[i] = 0;                      // reset for next replay
    }
    if (b == 0 && t == 0) g_offs[NN] = EP; // total is constant
}

// ---------------- scatter edges into destination-sorted order ----------------
__global__ void scatter_kernel(const int* __restrict__ ei) {
    int e = blockIdx.x * blockDim.x + threadIdx.x;
    if (e < EP) {
        int row, col;
        if (e < EE) { row = ei[e]; col = ei[EE + e]; }
        else        { row = e - EE; col = row; }
        int pos = atomicAdd(&g_cursor[row], 1);
        g_scol[pos] = col;
    }
}

// -------- per-node attention aggregation (one warp per node, fp16 gathers) ---
// 2x unrolled edge loop, uint2 per lane. LOCKED: L2-throughput bound (333MB);
// 4x unroll, half-warp-per-edge, and 2-warp-per-node all measured worse.
__global__ __launch_bounds__(256) void aggregate_kernel(
    const float* __restrict__ bias, float* __restrict__ out)
{
    const int n = (blockIdx.x * blockDim.x + threadIdx.x) >> 5;
    const int lane = threadIdx.x & 31;
    if (n >= NN) return;

    uint2 qu = *reinterpret_cast<const uint2*>(&g_Qh[(size_t)n * FF + lane * 4]);
    const float2 q0 = __half22float2(*reinterpret_cast<__half2*>(&qu.x));
    const float2 q1 = __half22float2(*reinterpret_cast<__half2*>(&qu.y));

    float a0 = 0.f, a1 = 0.f, a2 = 0.f, a3 = 0.f;
    float denom = 0.f;

    const int s = g_offs[n];
    const int e = g_offs[n + 1];
    int p = s;

    for (; p + 2 <= e; p += 2) {
        const int c0 = g_scol[p];
        const int c1 = g_scol[p + 1];
        uint2 k0 = *reinterpret_cast<const uint2*>(&g_Kh[(size_t)c0 * FF + lane * 4]);
        uint2 k1 = *reinterpret_cast<const uint2*>(&g_Kh[(size_t)c1 * FF + lane * 4]);
        uint2 v0 = *reinterpret_cast<const uint2*>(&g_Vh[(size_t)c0 * FF + lane * 4]);
        uint2 v1 = *reinterpret_cast<const uint2*>(&g_Vh[(size_t)c1 * FF + lane * 4]);

        float2 ka = __half22float2(*reinterpret_cast<__half2*>(&k0.x));
        float2 kb = __half22float2(*reinterpret_cast<__half2*>(&k0.y));
        float d0 = q0.x * ka.x + q0.y * ka.y + q1.x * kb.x + q1.y * kb.y;
        ka = __half22float2(*reinterpret_cast<__half2*>(&k1.x));
        kb = __half22float2(*reinterpret_cast<__half2*>(&k1.y));
        float d1 = q0.x * ka.x + q0.y * ka.y + q1.x * kb.x + q1.y * kb.y;

        d0 += __shfl_xor_sync(0xffffffff, d0, 1);
        d1 += __shfl_xor_sync(0xffffffff, d1, 1);
        d0 += __shfl_xor_sync(0xffffffff, d0, 2);
        d1 += __shfl_xor_sync(0xffffffff, d1, 2);

        const float w0 = __expf(d0 * 0.25f);
        const float w1 = __expf(d1 * 0.25f);

        float2 va = __half22float2(*reinterpret_cast<__half2*>(&v0.x));
        float2 vb = __half22float2(*reinterpret_cast<__half2*>(&v0.y));
        a0 = fmaf(w0, va.x, a0); a1 = fmaf(w0, va.y, a1);
        a2 = fmaf(w0, vb.x, a2); a3 = fmaf(w0, vb.y, a3);
        va = __half22float2(*reinterpret_cast<__half2*>(&v1.x));
        vb = __half22float2(*reinterpret_cast<__half2*>(&v1.y));
        a0 = fmaf(w1, va.x, a0); a1 = fmaf(w1, va.y, a1);
        a2 = fmaf(w1, vb.x, a2); a3 = fmaf(w1, vb.y, a3);
        denom += w0 + w1;
    }
    for (; p < e; p++) {
        const int c0 = g_scol[p];
        uint2 k0 = *reinterpret_cast<const uint2*>(&g_Kh[(size_t)c0 * FF + lane * 4]);
        float2 ka = __half22float2(*reinterpret_cast<__half2*>(&k0.x));
        float2 kb = __half22float2(*reinterpret_cast<__half2*>(&k0.y));
        float d0 = q0.x * ka.x + q0.y * ka.y + q1.x * kb.x + q1.y * kb.y;
        d0 += __shfl_xor_sync(0xffffffff, d0, 1);
        d0 += __shfl_xor_sync(0xffffffff, d0, 2);
        const float w0 = __expf(d0 * 0.25f);
        uint2 v0 = *reinterpret_cast<const uint2*>(&g_Vh[(size_t)c0 * FF + lane * 4]);
        float2 va = __half22float2(*reinterpret_cast<__half2*>(&v0.x));
        float2 vb = __half22float2(*reinterpret_cast<__half2*>(&v0.y));
        a0 = fmaf(w0, va.x, a0); a1 = fmaf(w0, va.y, a1);
        a2 = fmaf(w0, vb.x, a2); a3 = fmaf(w0, vb.y, a3);
        denom += w0;
    }

    const float inv = 1.f / denom;   // >= 1 edge guaranteed (self loop)
    const float4 b = *reinterpret_cast<const float4*>(&bias[lane * 4]);
    float4 o;
    o.x = fmaf(a0, inv, b.x);
    o.y = fmaf(a1, inv, b.y);
    o.z = fmaf(a2, inv, b.z);
    o.w = fmaf(a3, inv, b.w);
    *reinterpret_cast<float4*>(&out[(size_t)n * FF + lane * 4]) = o;
}

// ---------------- launch ----------------
extern "C" void kernel_launch(void* const* d_in, const int* in_sizes, int n_in,
                              void* d_out, int out_size)
{
    const float* x    = (const float*)d_in[0];
    const int*   ei   = (const int*)d_in[1];     // JAX x64 disabled -> int32
    const int*   idix = (const int*)d_in[2];
    const float* Wq   = (const float*)d_in[3];
    const float* bq   = (const float*)d_in[4];
    const float* Wk   = (const float*)d_in[5];
    const float* bk   = (const float*)d_in[6];
    const float* Wv   = (const float*)d_in[7];
    const float* Wid  = (const float*)d_in[8];
    const float* bo   = (const float*)d_in[9];
    float* out = (float*)d_out;

    static cudaStream_t s2 = nullptr;
    static cudaEvent_t evA = nullptr, evB = nullptr;
    static bool init_done = false;
    if (!init_done) {
        cudaFuncSetAttribute(gemm3_kernel,
                             cudaFuncAttributeMaxDynamicSharedMemorySize, GEMM_SMEM);
        cudaStreamCreateWithFlags(&s2, cudaStreamNonBlocking);
        cudaEventCreateWithFlags(&evA, cudaEventDisableTiming);
        cudaEventCreateWithFlags(&evB, cudaEventDisableTiming);
        init_done = true;
    }

    // prep+hist fused on s0; scan chain forks to s2 (hides under gemm);
    // join before aggregate. gemm3 stays kernel #4 for ncu continuity.
    prep_hist_kernel<<<XB + WB + HB, 256>>>(x, Wq, Wk, Wv, ei);       // #1 (s0)
    cudaEventRecord(evA, 0);
    cudaStreamWaitEvent(s2, evA, 0);

    scan1_kernel<<<NSB, SB, 0, s2>>>();                               // #2 (s2)
    scan23_kernel<<<NSB, SB, 0, s2>>>();                              // #3 (s2)
    dim3 ggrid((NN + 127) / 128, 3);
    gemm3_kernel<<<ggrid, 256, GEMM_SMEM>>>(bq, bk);                  // #4 (s0)
    scatter_kernel<<<(EP + 255) / 256, 256, 0, s2>>>(ei);             // #5 (s2)
    idgemm_kernel<<<(NID + IDB - 1) / IDB, 256>>>(x, idix, Wid);      // #6 (s0)

    cudaEventRecord(evB, s2);
    cudaStreamWaitEvent(0, evB, 0);

    // fused attention softmax + aggregation, one warp per node
    aggregate_kernel<<<(NN * 32 + 255) / 256, 256>>>(bo, out);        // #7 (s0)
}